// round 1
// baseline (speedup 1.0000x reference)
#include <cuda_runtime.h>

#define N_TOK 512
#define E_DIM 256
#define HID   150
#define HPAD  160

// Scratch for precomputed A_i = g_i @ W1[0:256] + b1  and  B_j = g_j @ W1[256:512]
__device__ float g_sA[N_TOK * HPAD];
__device__ float g_sB[N_TOK * HPAD];

struct SmemAB {
    float g[64][E_DIM];   // 64 KB
    float w[32][HPAD];    // 20 KB
};

struct SmemPW {
    float gi[8][E_DIM];   // 8 KB
    float gj[8][E_DIM];   // 8 KB
    float w[32][HPAD];    // 20 KB  (staged W1c / W2 chunks)
    float h1[64][HPAD];   // 40 KB
    float w3[HPAD];       // 0.64 KB
};

// ---------------------------------------------------------------------------
// Kernel 1: A/B precompute.  grid (8, 2): y==0 -> A (adds b1), y==1 -> B.
// M=64 rows, N=150(+pad), K=256. Thread tile: 4 rows x 10 cols.
// ---------------------------------------------------------------------------
__global__ __launch_bounds__(256, 2)
void ab_kernel(const float* __restrict__ G, const float* __restrict__ W1,
               const float* __restrict__ b1) {
    extern __shared__ char smemraw[];
    SmemAB& s = *reinterpret_cast<SmemAB*>(smemraw);
    const int tid = threadIdx.x;
    const int tx = tid & 15, ty = tid >> 4;
    const int r0 = blockIdx.x * 64;
    const int variant = blockIdx.y;                 // 0 = A, 1 = B
    const float* W = W1 + variant * E_DIM * HID;
    float* outbuf = variant ? g_sB : g_sA;

    for (int idx = tid; idx < 64 * E_DIM; idx += 256)
        s.g[idx >> 8][idx & 255] = G[(r0 + (idx >> 8)) * E_DIM + (idx & 255)];

    float acc[4][10];
    #pragma unroll
    for (int m = 0; m < 4; m++)
        #pragma unroll
        for (int n = 0; n < 10; n++) {
            int h = tx * 10 + n;
            acc[m][n] = (variant == 0 && h < HID) ? b1[h] : 0.f;
        }

    for (int kk = 0; kk < E_DIM; kk += 32) {
        __syncthreads();
        for (int idx = tid; idx < 32 * HPAD; idx += 256) {
            int r = idx / HPAD, c = idx % HPAD;
            s.w[r][c] = (c < HID) ? W[(kk + r) * HID + c] : 0.f;
        }
        __syncthreads();
        #pragma unroll 8
        for (int e = 0; e < 32; e++) {
            float a[4];
            #pragma unroll
            for (int m = 0; m < 4; m++) a[m] = s.g[ty + 16 * m][kk + e];
            float w[10];
            #pragma unroll
            for (int n = 0; n < 10; n++) w[n] = s.w[e][tx * 10 + n];
            #pragma unroll
            for (int m = 0; m < 4; m++)
                #pragma unroll
                for (int n = 0; n < 10; n++)
                    acc[m][n] = fmaf(a[m], w[n], acc[m][n]);
        }
    }
    #pragma unroll
    for (int m = 0; m < 4; m++) {
        int r = r0 + ty + 16 * m;
        #pragma unroll
        for (int n = 0; n < 10; n++)
            outbuf[r * HPAD + tx * 10 + n] = acc[m][n];
    }
}

// ---------------------------------------------------------------------------
// Kernel 2: fused pairwise MLP. One block per 8x8 pair tile (grid 64x64).
// 64 pairs, thread = 4 pairs x 10 hidden. Pair p = ii*8+jj; thread ty owns
// pairs {ty, ty+16, ty+32, ty+48} -> jj constant per thread (= ty&7).
// ---------------------------------------------------------------------------
__global__ __launch_bounds__(256, 2)
void pw_kernel(const float* __restrict__ G, const float* __restrict__ ms,
               const float* __restrict__ W1, const float* __restrict__ W2,
               const float* __restrict__ b2, const float* __restrict__ W3,
               const float* __restrict__ b3, float* __restrict__ out) {
    extern __shared__ char smemraw[];
    SmemPW& s = *reinterpret_cast<SmemPW*>(smemraw);
    const int tid = threadIdx.x;
    const int tx = tid & 15, ty = tid >> 4;
    const int i0 = blockIdx.y * 8, j0 = blockIdx.x * 8;

    for (int idx = tid; idx < 8 * E_DIM; idx += 256) {
        int r = idx >> 8, c = idx & 255;
        s.gi[r][c] = G[(i0 + r) * E_DIM + c];
        s.gj[r][c] = G[(j0 + r) * E_DIM + c];
    }
    if (tid < HPAD) s.w3[tid] = (tid < HID) ? W3[tid] : 0.f;

    const int jjc = ty & 7;
    int ii[4];
    #pragma unroll
    for (int m = 0; m < 4; m++) ii[m] = (ty + 16 * m) >> 3;

    // ---- GEMM1: h1 = relu(A_i + B_j + (gi*gj) @ W1c)  (b1 folded into A) ----
    float acc[4][10];
    #pragma unroll
    for (int m = 0; m < 4; m++) {
        int gi_row = i0 + ii[m], gj_row = j0 + jjc;
        #pragma unroll
        for (int n = 0; n < 10; n++) {
            int h = tx * 10 + n;
            acc[m][n] = (h < HID) ? (g_sA[gi_row * HPAD + h] + g_sB[gj_row * HPAD + h]) : 0.f;
        }
    }
    const float* W1c = W1 + 2 * E_DIM * HID;
    for (int kk = 0; kk < E_DIM; kk += 32) {
        __syncthreads();
        for (int idx = tid; idx < 32 * HPAD; idx += 256) {
            int r = idx / HPAD, c = idx % HPAD;
            s.w[r][c] = (c < HID) ? W1c[(kk + r) * HID + c] : 0.f;
        }
        __syncthreads();
        #pragma unroll 8
        for (int e = 0; e < 32; e++) {
            float bv = s.gj[jjc][kk + e];
            float a[4];
            #pragma unroll
            for (int m = 0; m < 4; m++) a[m] = s.gi[ii[m]][kk + e] * bv;
            float w[10];
            #pragma unroll
            for (int n = 0; n < 10; n++) w[n] = s.w[e][tx * 10 + n];
            #pragma unroll
            for (int m = 0; m < 4; m++)
                #pragma unroll
                for (int n = 0; n < 10; n++)
                    acc[m][n] = fmaf(a[m], w[n], acc[m][n]);
        }
    }
    // relu -> SMEM h1 (pad cols are exactly 0: zero init + zero W pads)
    #pragma unroll
    for (int m = 0; m < 4; m++) {
        int p = ty + 16 * m;
        #pragma unroll
        for (int n = 0; n < 10; n++)
            s.h1[p][tx * 10 + n] = fmaxf(acc[m][n], 0.f);
    }

    // ---- GEMM2: h2 = relu(h1 @ W2 + b2) ----
    #pragma unroll
    for (int m = 0; m < 4; m++)
        #pragma unroll
        for (int n = 0; n < 10; n++) {
            int h = tx * 10 + n;
            acc[m][n] = (h < HID) ? b2[h] : 0.f;
        }
    for (int kk = 0; kk < HPAD; kk += 32) {
        __syncthreads();   // also orders h1 stores before first read
        for (int idx = tid; idx < 32 * HPAD; idx += 256) {
            int r = idx / HPAD, c = idx % HPAD;
            s.w[r][c] = (c < HID && (kk + r) < HID) ? W2[(kk + r) * HID + c] : 0.f;
        }
        __syncthreads();
        #pragma unroll 8
        for (int e = 0; e < 32; e++) {
            float a[4];
            #pragma unroll
            for (int m = 0; m < 4; m++) a[m] = s.h1[ty + 16 * m][kk + e];
            float w[10];
            #pragma unroll
            for (int n = 0; n < 10; n++) w[n] = s.w[e][tx * 10 + n];
            #pragma unroll
            for (int m = 0; m < 4; m++)
                #pragma unroll
                for (int n = 0; n < 10; n++)
                    acc[m][n] = fmaf(a[m], w[n], acc[m][n]);
        }
    }

    // ---- layer 3: s = relu(h2) . W3 ; reduce over the 16 tx lanes ----
    float part[4];
    #pragma unroll
    for (int m = 0; m < 4; m++) {
        float v = 0.f;
        #pragma unroll
        for (int n = 0; n < 10; n++)
            v = fmaf(fmaxf(acc[m][n], 0.f), s.w3[tx * 10 + n], v);
        part[m] = v;
    }
    #pragma unroll
    for (int m = 0; m < 4; m++) {
        #pragma unroll
        for (int off = 8; off >= 1; off >>= 1)
            part[m] += __shfl_xor_sync(0xffffffffu, part[m], off, 16);
    }
    if (tx == 0) {
        float bb = b3[0];
        #pragma unroll
        for (int m = 0; m < 4; m++) {
            int p = ty + 16 * m;
            int i = i0 + (p >> 3), j = j0 + (p & 7);
            out[i * N_TOK + j] = (ms[i] + ms[j] + part[m] + bb) * (1.f / 3.f);
        }
    }
}

// ---------------------------------------------------------------------------
extern "C" void kernel_launch(void* const* d_in, const int* in_sizes, int n_in,
                              void* d_out, int out_size) {
    const float* G  = (const float*)d_in[0];  // (1,512,256)
    const float* ms = (const float*)d_in[1];  // (1,512,1)
    const float* W1 = (const float*)d_in[2];  // (768,150)
    const float* b1 = (const float*)d_in[3];  // (150)
    const float* W2 = (const float*)d_in[4];  // (150,150)
    const float* b2 = (const float*)d_in[5];  // (150)
    const float* W3 = (const float*)d_in[6];  // (150,1)
    const float* b3 = (const float*)d_in[7];  // (1)
    float* out = (float*)d_out;               // (1,512,512,1)

    cudaFuncSetAttribute(ab_kernel, cudaFuncAttributeMaxDynamicSharedMemorySize,
                         (int)sizeof(SmemAB));
    cudaFuncSetAttribute(pw_kernel, cudaFuncAttributeMaxDynamicSharedMemorySize,
                         (int)sizeof(SmemPW));

    ab_kernel<<<dim3(8, 2), 256, sizeof(SmemAB)>>>(G, W1, b1);
    pw_kernel<<<dim3(64, 64), 256, sizeof(SmemPW)>>>(G, ms, W1, W2, b2, W3, b3, out);
}

// round 2
// speedup vs baseline: 3.6990x; 3.6990x over previous
#include <cuda_runtime.h>
#include <cstdint>

#define N_TOK 512
#define E_DIM 256
#define HID   150
#define NPAD  160
#define APAD  168

// Prepped device scratch
__device__ float g_sA[N_TOK * APAD];        // A_i = g_i@W1[0:256] + b1, padded cols zero
__device__ float g_sB[N_TOK * APAD];        // B_j = g_j@W1[256:512]
__device__ float g_img1[E_DIM * APAD];      // W1c tf32-rounded, [k][n], pad cols zero
__device__ float g_img2[NPAD * APAD];       // W2  tf32-rounded, [k][n], pad rows/cols zero

// ---------------------------------------------------------------------------
__device__ __forceinline__ uint32_t tf32u(float x) {
    uint32_t r; asm("cvt.rna.tf32.f32 %0, %1;" : "=r"(r) : "f"(x)); return r;
}
__device__ __forceinline__ void mma8(float* d, uint32_t a0, uint32_t a1,
                                     uint32_t a2, uint32_t a3,
                                     uint32_t b0, uint32_t b1) {
    asm volatile(
        "mma.sync.aligned.m16n8k8.row.col.f32.tf32.tf32.f32 "
        "{%0,%1,%2,%3}, {%4,%5,%6,%7}, {%8,%9}, {%0,%1,%2,%3};"
        : "+f"(d[0]), "+f"(d[1]), "+f"(d[2]), "+f"(d[3])
        : "r"(a0), "r"(a1), "r"(a2), "r"(a3), "r"(b0), "r"(b1));
}
__device__ __forceinline__ void cpasync16(uint32_t dst, const float4* src) {
    asm volatile("cp.async.cg.shared.global [%0], [%1], 16;" :: "r"(dst), "l"(src));
}
#define CP_COMMIT() asm volatile("cp.async.commit_group;")
#define CP_WAIT0()  asm volatile("cp.async.wait_group 0;" ::: "memory")

// 32 x APAD floats = 1344 float4 per chunk
#define CHUNK4 (32 * APAD / 4)
__device__ __forceinline__ void stage_chunk(uint32_t smem_dst, const float4* src, int tid) {
    #pragma unroll
    for (int t = 0; t < 6; t++) {
        int idx = tid + t * 256;
        if (idx < CHUNK4) cpasync16(smem_dst + idx * 16, src + idx);
    }
    CP_COMMIT();
}

// ---------------------------------------------------------------------------
// Prep 1: tf32-round + pad the two pairwise-GEMM weight images.
// ---------------------------------------------------------------------------
__global__ void wprep(const float* __restrict__ W1, const float* __restrict__ W2) {
    int idx = blockIdx.x * 256 + threadIdx.x;
    if (idx < E_DIM * APAD) {
        int k = idx / APAD, c = idx - k * APAD;
        float v = (c < HID) ? W1[(2 * E_DIM + k) * HID + c] : 0.f;
        g_img1[idx] = __uint_as_float(tf32u(v));
    }
    if (idx < NPAD * APAD) {
        int k = idx / APAD, c = idx - k * APAD;
        float v = (k < HID && c < HID) ? W2[k * HID + c] : 0.f;
        g_img2[idx] = __uint_as_float(tf32u(v));
    }
}

// ---------------------------------------------------------------------------
// Prep 2: sA/sB precompute (fp32 FFMA). grid (8,2): y==0 -> A (+b1), y==1 -> B.
// ---------------------------------------------------------------------------
struct SmemAB {
    float g[64][E_DIM];
    float w[32][APAD];
};

__global__ __launch_bounds__(256, 2)
void ab_kernel(const float* __restrict__ G, const float* __restrict__ W1,
               const float* __restrict__ b1) {
    extern __shared__ char smemraw[];
    SmemAB& s = *reinterpret_cast<SmemAB*>(smemraw);
    const int tid = threadIdx.x;
    const int tx = tid & 15, ty = tid >> 4;
    const int r0 = blockIdx.x * 64;
    const int variant = blockIdx.y;
    const float* W = W1 + variant * E_DIM * HID;
    float* outbuf = variant ? g_sB : g_sA;

    for (int idx = tid; idx < 64 * E_DIM; idx += 256)
        s.g[idx >> 8][idx & 255] = G[(r0 + (idx >> 8)) * E_DIM + (idx & 255)];

    float acc[4][10];
    #pragma unroll
    for (int m = 0; m < 4; m++)
        #pragma unroll
        for (int n = 0; n < 10; n++) {
            int h = tx * 10 + n;
            acc[m][n] = (variant == 0 && h < HID) ? b1[h] : 0.f;
        }

    for (int kk = 0; kk < E_DIM; kk += 32) {
        __syncthreads();
        for (int idx = tid; idx < 32 * APAD; idx += 256) {
            int r = idx / APAD, c = idx - r * APAD;
            s.w[r][c] = (c < HID) ? W[(kk + r) * HID + c] : 0.f;
        }
        __syncthreads();
        #pragma unroll 8
        for (int e = 0; e < 32; e++) {
            float a[4];
            #pragma unroll
            for (int m = 0; m < 4; m++) a[m] = s.g[ty + 16 * m][kk + e];
            float w[10];
            #pragma unroll
            for (int n = 0; n < 10; n++) w[n] = s.w[e][tx * 10 + n];
            #pragma unroll
            for (int m = 0; m < 4; m++)
                #pragma unroll
                for (int n = 0; n < 10; n++)
                    acc[m][n] = fmaf(a[m], w[n], acc[m][n]);
        }
    }
    #pragma unroll
    for (int m = 0; m < 4; m++) {
        int r = r0 + ty + 16 * m;
        #pragma unroll
        for (int n = 0; n < 10; n++)
            outbuf[r * APAD + tx * 10 + n] = acc[m][n];
    }
    // zero pad cols 160..167
    for (int idx = tid; idx < 64 * 8; idx += 256)
        outbuf[(r0 + (idx >> 3)) * APAD + NPAD + (idx & 7)] = 0.f;
}

// ---------------------------------------------------------------------------
// Main kernel: 128 pairs (16 i x 8 j) x 160 hidden per block, tf32 mma.sync.
// 8 warps: warp_m = wid&3 (32 rows each), warp_n = wid>>2 (80 cols each).
// Warp fragment grid: 2 (m16) x 10 (n8).
// ---------------------------------------------------------------------------
struct SmemPW {
    float gi[16][260];
    float gj[8][260];
    float w[2][32][APAD];
    float h1[128][172];
    float sAi[16][APAD];
    float sBj[8][APAD];
    float b2s[APAD];
    float w3s[APAD];
    float msi[16], msj[8];
    float part[128][2];
    float b3s;
};

__global__ __launch_bounds__(256, 1)
void pw_kernel(const float* __restrict__ G, const float* __restrict__ ms,
               const float* __restrict__ b2, const float* __restrict__ W3,
               const float* __restrict__ b3, float* __restrict__ out) {
    extern __shared__ char smemraw[];
    SmemPW& s = *reinterpret_cast<SmemPW*>(smemraw);
    const int tid  = threadIdx.x;
    const int lane = tid & 31, wid = tid >> 5;
    const int wm = wid & 3, wn = wid >> 2;
    const int qrow = lane >> 2, qk = lane & 3;
    const int i0 = blockIdx.y * 16, j0 = blockIdx.x * 8;

    uint32_t wsm[2];
    wsm[0] = (uint32_t)__cvta_generic_to_shared(&s.w[0][0][0]);
    wsm[1] = wsm[0] + 32 * APAD * 4;

    // kick off GEMM1 chunk 0 stage
    stage_chunk(wsm[0], (const float4*)g_img1, tid);

    // ---- block-wide loads ----
    const float4* G4 = (const float4*)G;
    for (int idx = tid; idx < 16 * 64; idx += 256) {
        int r = idx >> 6, c = idx & 63;
        *(float4*)&s.gi[r][c * 4] = G4[(i0 + r) * 64 + c];
    }
    for (int idx = tid; idx < 8 * 64; idx += 256) {
        int r = idx >> 6, c = idx & 63;
        *(float4*)&s.gj[r][c * 4] = G4[(j0 + r) * 64 + c];
    }
    const float4* A4 = (const float4*)g_sA;
    const float4* B4 = (const float4*)g_sB;
    for (int idx = tid; idx < 16 * 42; idx += 256) {
        int r = idx / 42, c = idx - r * 42;
        *(float4*)&s.sAi[r][c * 4] = A4[(i0 + r) * 42 + c];
    }
    for (int idx = tid; idx < 8 * 42; idx += 256) {
        int r = idx / 42, c = idx - r * 42;
        *(float4*)&s.sBj[r][c * 4] = B4[(j0 + r) * 42 + c];
    }
    if (tid < APAD) {
        s.b2s[tid] = (tid < HID) ? b2[tid] : 0.f;
        s.w3s[tid] = (tid < HID) ? W3[tid] : 0.f;
    }
    if (tid < 16) s.msi[tid] = ms[i0 + tid];
    if (tid < 8)  s.msj[tid] = ms[j0 + tid];
    if (tid == 0) s.b3s = b3[0];

    CP_WAIT0();
    __syncthreads();

    // ---- GEMM1: acc = sA_i + sB_j + (gi*gj) @ W1c ----
    float acc[2][10][4];
    #pragma unroll
    for (int fm = 0; fm < 2; fm++) {
        int r0 = wm * 32 + fm * 16 + qrow;
        int ib = r0 >> 3;   // local i (qrow<8 so same for all quad rows)
        #pragma unroll
        for (int nf = 0; nf < 10; nf++) {
            int c0 = wn * 80 + nf * 8 + 2 * qk, c1 = c0 + 1;
            acc[fm][nf][0] = s.sAi[ib][c0]     + s.sBj[qrow][c0];
            acc[fm][nf][1] = s.sAi[ib][c1]     + s.sBj[qrow][c1];
            acc[fm][nf][2] = s.sAi[ib + 1][c0] + s.sBj[qrow][c0];
            acc[fm][nf][3] = s.sAi[ib + 1][c1] + s.sBj[qrow][c1];
        }
    }

    const float4* img1_4 = (const float4*)g_img1;
    const float4* img2_4 = (const float4*)g_img2;

    for (int c = 0; c < 8; c++) {
        // prefetch next chunk (at c==7, prefetch GEMM2 chunk 0)
        if (c < 7) stage_chunk(wsm[(c + 1) & 1], img1_4 + (c + 1) * CHUNK4, tid);
        else       stage_chunk(wsm[0], img2_4, tid);
        const float (*wb)[APAD] = s.w[c & 1];
        #pragma unroll
        for (int ks = 0; ks < 4; ks++) {
            int kk = c * 32 + ks * 8;
            uint32_t b[10][2];
            #pragma unroll
            for (int nf = 0; nf < 10; nf++) {
                int n = wn * 80 + nf * 8 + qrow;
                b[nf][0] = __float_as_uint(wb[ks * 8 + qk][n]);
                b[nf][1] = __float_as_uint(wb[ks * 8 + qk + 4][n]);
            }
            #pragma unroll
            for (int fm = 0; fm < 2; fm++) {
                int ib = wm * 4 + fm * 2;
                float gj0 = s.gj[qrow][kk + qk], gj4 = s.gj[qrow][kk + qk + 4];
                uint32_t a0 = tf32u(s.gi[ib][kk + qk] * gj0);
                uint32_t a1 = tf32u(s.gi[ib + 1][kk + qk] * gj0);
                uint32_t a2 = tf32u(s.gi[ib][kk + qk + 4] * gj4);
                uint32_t a3 = tf32u(s.gi[ib + 1][kk + qk + 4] * gj4);
                #pragma unroll
                for (int nf = 0; nf < 10; nf++)
                    mma8(acc[fm][nf], a0, a1, a2, a3, b[nf][0], b[nf][1]);
            }
        }
        CP_WAIT0();
        __syncthreads();
    }

    // ---- h1 = relu(acc), tf32-rounded, to SMEM; re-init acc with b2 ----
    #pragma unroll
    for (int fm = 0; fm < 2; fm++) {
        int r0 = wm * 32 + fm * 16 + qrow, r1 = r0 + 8;
        #pragma unroll
        for (int nf = 0; nf < 10; nf++) {
            int c0 = wn * 80 + nf * 8 + 2 * qk, c1 = c0 + 1;
            s.h1[r0][c0] = __uint_as_float(tf32u(fmaxf(acc[fm][nf][0], 0.f)));
            s.h1[r0][c1] = __uint_as_float(tf32u(fmaxf(acc[fm][nf][1], 0.f)));
            s.h1[r1][c0] = __uint_as_float(tf32u(fmaxf(acc[fm][nf][2], 0.f)));
            s.h1[r1][c1] = __uint_as_float(tf32u(fmaxf(acc[fm][nf][3], 0.f)));
            float v0 = s.b2s[c0], v1 = s.b2s[c1];
            acc[fm][nf][0] = v0; acc[fm][nf][1] = v1;
            acc[fm][nf][2] = v0; acc[fm][nf][3] = v1;
        }
    }
    __syncthreads();

    // ---- GEMM2: acc = b2 + h1 @ W2  (K = 160, 5 chunks) ----
    for (int c = 0; c < 5; c++) {
        if (c < 4) stage_chunk(wsm[(c + 1) & 1], img2_4 + (c + 1) * CHUNK4, tid);
        const float (*wb)[APAD] = s.w[c & 1];
        #pragma unroll
        for (int ks = 0; ks < 4; ks++) {
            int kk = c * 32 + ks * 8;
            uint32_t b[10][2];
            #pragma unroll
            for (int nf = 0; nf < 10; nf++) {
                int n = wn * 80 + nf * 8 + qrow;
                b[nf][0] = __float_as_uint(wb[ks * 8 + qk][n]);
                b[nf][1] = __float_as_uint(wb[ks * 8 + qk + 4][n]);
            }
            #pragma unroll
            for (int fm = 0; fm < 2; fm++) {
                int r0 = wm * 32 + fm * 16 + qrow;
                uint32_t a0 = __float_as_uint(s.h1[r0][kk + qk]);
                uint32_t a1 = __float_as_uint(s.h1[r0 + 8][kk + qk]);
                uint32_t a2 = __float_as_uint(s.h1[r0][kk + qk + 4]);
                uint32_t a3 = __float_as_uint(s.h1[r0 + 8][kk + qk + 4]);
                #pragma unroll
                for (int nf = 0; nf < 10; nf++)
                    mma8(acc[fm][nf], a0, a1, a2, a3, b[nf][0], b[nf][1]);
            }
        }
        CP_WAIT0();
        __syncthreads();
    }

    // ---- layer 3: s = relu(h2) . W3, quad-shuffle reduce, combine ----
    float p0[2] = {0.f, 0.f}, p1[2] = {0.f, 0.f};
    #pragma unroll
    for (int fm = 0; fm < 2; fm++)
        #pragma unroll
        for (int nf = 0; nf < 10; nf++) {
            int c0 = wn * 80 + nf * 8 + 2 * qk, c1 = c0 + 1;
            float w30 = s.w3s[c0], w31 = s.w3s[c1];
            p0[fm] = fmaf(fmaxf(acc[fm][nf][0], 0.f), w30,
                     fmaf(fmaxf(acc[fm][nf][1], 0.f), w31, p0[fm]));
            p1[fm] = fmaf(fmaxf(acc[fm][nf][2], 0.f), w30,
                     fmaf(fmaxf(acc[fm][nf][3], 0.f), w31, p1[fm]));
        }
    #pragma unroll
    for (int fm = 0; fm < 2; fm++) {
        #pragma unroll
        for (int off = 1; off <= 2; off <<= 1) {
            p0[fm] += __shfl_xor_sync(0xffffffffu, p0[fm], off);
            p1[fm] += __shfl_xor_sync(0xffffffffu, p1[fm], off);
        }
    }
    if (qk == 0) {
        #pragma unroll
        for (int fm = 0; fm < 2; fm++) {
            int r0 = wm * 32 + fm * 16 + qrow;
            s.part[r0][wn]     = p0[fm];
            s.part[r0 + 8][wn] = p1[fm];
        }
    }
    __syncthreads();

    if (tid < 128) {
        int il = tid >> 3, jl = tid & 7;
        float sv = s.part[tid][0] + s.part[tid][1] + s.b3s;
        out[(i0 + il) * N_TOK + (j0 + jl)] =
            (s.msi[il] + s.msj[jl] + sv) * (1.f / 3.f);
    }
}

// ---------------------------------------------------------------------------
extern "C" void kernel_launch(void* const* d_in, const int* in_sizes, int n_in,
                              void* d_out, int out_size) {
    const float* G  = (const float*)d_in[0];
    const float* ms = (const float*)d_in[1];
    const float* W1 = (const float*)d_in[2];
    const float* b1 = (const float*)d_in[3];
    const float* W2 = (const float*)d_in[4];
    const float* b2 = (const float*)d_in[5];
    const float* W3 = (const float*)d_in[6];
    const float* b3 = (const float*)d_in[7];
    float* out = (float*)d_out;

    cudaFuncSetAttribute(ab_kernel, cudaFuncAttributeMaxDynamicSharedMemorySize,
                         (int)sizeof(SmemAB));
    cudaFuncSetAttribute(pw_kernel, cudaFuncAttributeMaxDynamicSharedMemorySize,
                         (int)sizeof(SmemPW));

    wprep<<<(E_DIM * APAD + 255) / 256, 256>>>(W1, W2);
    ab_kernel<<<dim3(8, 2), 256, sizeof(SmemAB)>>>(G, W1, b1);
    pw_kernel<<<dim3(64, 32), 256, sizeof(SmemPW)>>>(G, ms, b2, W3, b3, out);
}

// round 5
// speedup vs baseline: 6.6033x; 1.7852x over previous
#include <cuda_runtime.h>
#include <cuda_fp16.h>
#include <cstdint>

#define N_TOK 512
#define E_DIM 256
#define HID   150
#define NPD   160           // padded hidden (N of both GEMMs)
#define WST   168           // weight image word-stride (half2 words per kpair)
#define IMG1W (128 * WST)   // GEMM1 weight image: 128 kpairs (K=256)
#define IMG2W (80  * WST)   // GEMM2 weight image: 80 kpairs (K=160)
#define CHUNK4 672          // 16 kpairs * 168 words / 4 per staged chunk

__device__ float    g_sA[N_TOK * NPD];
__device__ float    g_sB[N_TOK * NPD];
__device__ uint32_t g_img1[IMG1W];   // half2(W1c[2kp][n], W1c[2kp+1][n])
__device__ uint32_t g_img2[IMG2W];   // half2(W2 [2kp][n], W2 [2kp+1][n])

// ---------------- helpers ----------------
__device__ __forceinline__ uint32_t packh2(float lo, float hi) {
    __half2 h = __floats2half2_rn(lo, hi);
    return *reinterpret_cast<uint32_t*>(&h);
}
__device__ __forceinline__ void mma16(float* d, uint32_t a0, uint32_t a1,
                                      uint32_t a2, uint32_t a3,
                                      uint32_t b0, uint32_t b1) {
    asm volatile(
        "mma.sync.aligned.m16n8k16.row.col.f32.f16.f16.f32 "
        "{%0,%1,%2,%3}, {%4,%5,%6,%7}, {%8,%9}, {%0,%1,%2,%3};"
        : "+f"(d[0]), "+f"(d[1]), "+f"(d[2]), "+f"(d[3])
        : "r"(a0), "r"(a1), "r"(a2), "r"(a3), "r"(b0), "r"(b1));
}
__device__ __forceinline__ void cpasync16(uint32_t dst, const float4* src) {
    asm volatile("cp.async.cg.shared.global [%0], [%1], 16;" :: "r"(dst), "l"(src));
}
#define CP_COMMIT() asm volatile("cp.async.commit_group;")
#define CP_WAIT0()  asm volatile("cp.async.wait_group 0;" ::: "memory")

__device__ __forceinline__ void stage_chunk(uint32_t smem_dst, const float4* src, int tid) {
    #pragma unroll
    for (int t = 0; t < 3; t++) {
        int idx = tid + t * 256;
        if (idx < CHUNK4) cpasync16(smem_dst + idx * 16, src + idx);
    }
    CP_COMMIT();
}

// ---------------------------------------------------------------------------
// wprep: build fp16 half2 weight images [kpair][n], k-pairs packed in .b32.
// ---------------------------------------------------------------------------
__global__ void wprep(const float* __restrict__ W1, const float* __restrict__ W2) {
    int idx = blockIdx.x * 256 + threadIdx.x;
    if (idx < IMG1W) {
        int kp = idx / WST, n = idx - kp * WST;
        float lo = 0.f, hi = 0.f;
        if (n < HID) {
            lo = W1[(2 * E_DIM + 2 * kp)     * HID + n];
            hi = W1[(2 * E_DIM + 2 * kp + 1) * HID + n];
        }
        g_img1[idx] = packh2(lo, hi);
    }
    if (idx < IMG2W) {
        int kp = idx / WST, n = idx - kp * WST;
        float lo = 0.f, hi = 0.f;
        if (n < HID) {
            if (2 * kp     < HID) lo = W2[(2 * kp)     * HID + n];
            if (2 * kp + 1 < HID) hi = W2[(2 * kp + 1) * HID + n];
        }
        g_img2[idx] = packh2(lo, hi);
    }
}

// ---------------------------------------------------------------------------
// ab_kernel: exact fp32 sA/sB precompute (out stride NPD, pad cols zero).
// ---------------------------------------------------------------------------
struct SmemAB { float g[64][E_DIM]; float w[32][NPD]; };

__global__ __launch_bounds__(256, 2)
void ab_kernel(const float* __restrict__ G, const float* __restrict__ W1,
               const float* __restrict__ b1) {
    extern __shared__ char smemraw[];
    SmemAB& s = *reinterpret_cast<SmemAB*>(smemraw);
    const int tid = threadIdx.x, tx = tid & 15, ty = tid >> 4;
    const int r0 = blockIdx.x * 64, variant = blockIdx.y;
    const float* W = W1 + variant * E_DIM * HID;
    float* outbuf = variant ? g_sB : g_sA;

    for (int idx = tid; idx < 64 * E_DIM; idx += 256)
        s.g[idx >> 8][idx & 255] = G[(r0 + (idx >> 8)) * E_DIM + (idx & 255)];

    float acc[4][10];
    #pragma unroll
    for (int m = 0; m < 4; m++)
        #pragma unroll
        for (int n = 0; n < 10; n++) {
            int h = tx * 10 + n;
            acc[m][n] = (variant == 0 && h < HID) ? b1[h] : 0.f;
        }
    for (int kk = 0; kk < E_DIM; kk += 32) {
        __syncthreads();
        for (int idx = tid; idx < 32 * NPD; idx += 256) {
            int r = idx / NPD, c = idx - r * NPD;
            s.w[r][c] = (c < HID) ? W[(kk + r) * HID + c] : 0.f;
        }
        __syncthreads();
        #pragma unroll 8
        for (int e = 0; e < 32; e++) {
            float a[4];
            #pragma unroll
            for (int m = 0; m < 4; m++) a[m] = s.g[ty + 16 * m][kk + e];
            float w[10];
            #pragma unroll
            for (int n = 0; n < 10; n++) w[n] = s.w[e][tx * 10 + n];
            #pragma unroll
            for (int m = 0; m < 4; m++)
                #pragma unroll
                for (int n = 0; n < 10; n++)
                    acc[m][n] = fmaf(a[m], w[n], acc[m][n]);
        }
    }
    #pragma unroll
    for (int m = 0; m < 4; m++) {
        int r = r0 + ty + 16 * m;
        #pragma unroll
        for (int n = 0; n < 10; n++)
            outbuf[r * NPD + tx * 10 + n] = acc[m][n];
    }
}

// ---------------------------------------------------------------------------
// pw_kernel: 128 pairs (16 i x 8 j) x 160 hidden per block, fp16 m16n8k16.
// 8 warps: wm = wid&3 (32 rows), wn = wid>>2 (80 cols). 2 blocks/SM.
// ---------------------------------------------------------------------------
struct SmemPW {
    float    gi[16][260];     // 16640 B
    float    gj[8][260];      //  8320 B
    uint32_t w[2][16][WST];   // 21504 B  (16 kpairs x 168 half2 per buffer)
    uint32_t h1[128][84];     // 43008 B  (h1 as half2, k-pairs packed)
    float    sAi[16][NPD];    // 10240 B
    float    sBj[8][NPD];     //  5120 B
    float    b2s[NPD];
    float    w3s[NPD];
    float    msi[16], msj[8];
    float    part[128][2];
    float    b3s;
};

__global__ __launch_bounds__(256, 2)
void pw_kernel(const float* __restrict__ G, const float* __restrict__ ms,
               const float* __restrict__ b2, const float* __restrict__ W3,
               const float* __restrict__ b3, float* __restrict__ out) {
    extern __shared__ char smemraw[];
    SmemPW& s = *reinterpret_cast<SmemPW*>(smemraw);
    const int tid  = threadIdx.x;
    const int lane = tid & 31, wid = tid >> 5;
    const int wm = wid & 3, wn = wid >> 2;
    const int qrow = lane >> 2, qk = lane & 3;
    const int i0 = blockIdx.y * 16, j0 = blockIdx.x * 8;

    uint32_t wsm[2];
    wsm[0] = (uint32_t)__cvta_generic_to_shared(&s.w[0][0][0]);
    wsm[1] = wsm[0] + 16 * WST * 4;

    stage_chunk(wsm[0], (const float4*)g_img1, tid);

    // ---- block-wide loads ----
    const float4* G4 = (const float4*)G;
    for (int idx = tid; idx < 16 * 64; idx += 256) {
        int r = idx >> 6, c = idx & 63;
        *(float4*)&s.gi[r][c * 4] = G4[(i0 + r) * 64 + c];
    }
    for (int idx = tid; idx < 8 * 64; idx += 256) {
        int r = idx >> 6, c = idx & 63;
        *(float4*)&s.gj[r][c * 4] = G4[(j0 + r) * 64 + c];
    }
    const float4* A4 = (const float4*)g_sA;
    const float4* B4 = (const float4*)g_sB;
    for (int idx = tid; idx < 16 * 40; idx += 256) {
        int r = idx / 40, c = idx - r * 40;
        *(float4*)&s.sAi[r][c * 4] = A4[(i0 + r) * 40 + c];
    }
    for (int idx = tid; idx < 8 * 40; idx += 256) {
        int r = idx / 40, c = idx - r * 40;
        *(float4*)&s.sBj[r][c * 4] = B4[(j0 + r) * 40 + c];
    }
    if (tid < NPD) {
        s.b2s[tid] = (tid < HID) ? b2[tid] : 0.f;
        s.w3s[tid] = (tid < HID) ? W3[tid] : 0.f;
    }
    if (tid < 16) s.msi[tid] = ms[i0 + tid];
    if (tid < 8)  s.msj[tid] = ms[j0 + tid];
    if (tid == 0) s.b3s = b3[0];

    CP_WAIT0();
    __syncthreads();

    // ---- GEMM1 acc init: sA_i + sB_j (fp32, exact) ----
    const int ib0 = wm * 4;   // local i for fm=0 is ib0 + 0/1, fm=1 -> ib0+2/3
    float acc[2][10][4];
    #pragma unroll
    for (int fm = 0; fm < 2; fm++) {
        int ib = ib0 + fm * 2;
        #pragma unroll
        for (int nf = 0; nf < 10; nf++) {
            int c0 = wn * 80 + nf * 8 + 2 * qk, c1 = c0 + 1;
            acc[fm][nf][0] = s.sAi[ib][c0]     + s.sBj[qrow][c0];
            acc[fm][nf][1] = s.sAi[ib][c1]     + s.sBj[qrow][c1];
            acc[fm][nf][2] = s.sAi[ib + 1][c0] + s.sBj[qrow][c0];
            acc[fm][nf][3] = s.sAi[ib + 1][c1] + s.sBj[qrow][c1];
        }
    }

    const float4* img1_4 = (const float4*)g_img1;
    const float4* img2_4 = (const float4*)g_img2;

    // ---- GEMM1: += (gi*gj) @ W1c^T, K=256 = 8 chunks x 2 k-tiles ----
    for (int c = 0; c < 8; c++) {
        if (c < 7) stage_chunk(wsm[(c + 1) & 1], img1_4 + (c + 1) * CHUNK4, tid);
        else       stage_chunk(wsm[0], img2_4, tid);
        const uint32_t (*wb)[WST] = s.w[c & 1];
        #pragma unroll
        for (int t = 0; t < 2; t++) {
            uint32_t b[10][2];
            #pragma unroll
            for (int nf = 0; nf < 10; nf++) {
                int n = wn * 80 + nf * 8 + qrow;
                b[nf][0] = wb[t * 8 + qk][n];
                b[nf][1] = wb[t * 8 + qk + 4][n];
            }
            int k0 = (c * 2 + t) * 16 + 2 * qk;
            float2 gj0 = *(const float2*)&s.gj[qrow][k0];
            float2 gj8 = *(const float2*)&s.gj[qrow][k0 + 8];
            #pragma unroll
            for (int fm = 0; fm < 2; fm++) {
                int ib = ib0 + fm * 2;
                float2 gA0 = *(const float2*)&s.gi[ib][k0];
                float2 gB0 = *(const float2*)&s.gi[ib + 1][k0];
                float2 gA8 = *(const float2*)&s.gi[ib][k0 + 8];
                float2 gB8 = *(const float2*)&s.gi[ib + 1][k0 + 8];
                uint32_t a0 = packh2(gA0.x * gj0.x, gA0.y * gj0.y);
                uint32_t a1 = packh2(gB0.x * gj0.x, gB0.y * gj0.y);
                uint32_t a2 = packh2(gA8.x * gj8.x, gA8.y * gj8.y);
                uint32_t a3 = packh2(gB8.x * gj8.x, gB8.y * gj8.y);
                #pragma unroll
                for (int nf = 0; nf < 10; nf++)
                    mma16(acc[fm][nf], a0, a1, a2, a3, b[nf][0], b[nf][1]);
            }
        }
        CP_WAIT0();
        __syncthreads();
    }

    // ---- h1 = relu(acc) as half2 -> SMEM; re-init acc with b2 ----
    #pragma unroll
    for (int fm = 0; fm < 2; fm++) {
        int r0 = wm * 32 + fm * 16 + qrow;
        #pragma unroll
        for (int nf = 0; nf < 10; nf++) {
            int word = wn * 40 + nf * 4 + qk;
            s.h1[r0][word]     = packh2(fmaxf(acc[fm][nf][0], 0.f), fmaxf(acc[fm][nf][1], 0.f));
            s.h1[r0 + 8][word] = packh2(fmaxf(acc[fm][nf][2], 0.f), fmaxf(acc[fm][nf][3], 0.f));
            int c0 = wn * 80 + nf * 8 + 2 * qk;
            float v0 = s.b2s[c0], v1 = s.b2s[c0 + 1];
            acc[fm][nf][0] = v0; acc[fm][nf][1] = v1;
            acc[fm][nf][2] = v0; acc[fm][nf][3] = v1;
        }
    }
    __syncthreads();   // h1 visible; w buf0 already holds img2 chunk 0

    // ---- GEMM2: += h1 @ W2^T, K=160 = 5 chunks x 2 k-tiles ----
    for (int c = 0; c < 5; c++) {
        if (c < 4) stage_chunk(wsm[(c + 1) & 1], img2_4 + (c + 1) * CHUNK4, tid);
        const uint32_t (*wb)[WST] = s.w[c & 1];
        #pragma unroll
        for (int t = 0; t < 2; t++) {
            uint32_t b[10][2];
            #pragma unroll
            for (int nf = 0; nf < 10; nf++) {
                int n = wn * 80 + nf * 8 + qrow;
                b[nf][0] = wb[t * 8 + qk][n];
                b[nf][1] = wb[t * 8 + qk + 4][n];
            }
            int kw = (c * 2 + t) * 8 + qk;   // half2 word index into h1 row
            #pragma unroll
            for (int fm = 0; fm < 2; fm++) {
                int r0 = wm * 32 + fm * 16 + qrow;
                uint32_t a0 = s.h1[r0][kw];
                uint32_t a1 = s.h1[r0 + 8][kw];
                uint32_t a2 = s.h1[r0][kw + 4];
                uint32_t a3 = s.h1[r0 + 8][kw + 4];
                #pragma unroll
                for (int nf = 0; nf < 10; nf++)
                    mma16(acc[fm][nf], a0, a1, a2, a3, b[nf][0], b[nf][1]);
            }
        }
        CP_WAIT0();
        __syncthreads();
    }

    // ---- layer 3: relu(h2) . W3, quad reduce, combine ----
    float p0[2] = {0.f, 0.f}, p1[2] = {0.f, 0.f};
    #pragma unroll
    for (int fm = 0; fm < 2; fm++)
        #pragma unroll
        for (int nf = 0; nf < 10; nf++) {
            int c0 = wn * 80 + nf * 8 + 2 * qk;
            float w30 = s.w3s[c0], w31 = s.w3s[c0 + 1];
            p0[fm] = fmaf(fmaxf(acc[fm][nf][0], 0.f), w30,
                     fmaf(fmaxf(acc[fm][nf][1], 0.f), w31, p0[fm]));
            p1[fm] = fmaf(fmaxf(acc[fm][nf][2], 0.f), w30,
                     fmaf(fmaxf(acc[fm][nf][3], 0.f), w31, p1[fm]));
        }
    #pragma unroll
    for (int fm = 0; fm < 2; fm++) {
        #pragma unroll
        for (int off = 1; off <= 2; off <<= 1) {
            p0[fm] += __shfl_xor_sync(0xffffffffu, p0[fm], off);
            p1[fm] += __shfl_xor_sync(0xffffffffu, p1[fm], off);
        }
    }
    if (qk == 0) {
        #pragma unroll
        for (int fm = 0; fm < 2; fm++) {
            int r0 = wm * 32 + fm * 16 + qrow;
            s.part[r0][wn]     = p0[fm];
            s.part[r0 + 8][wn] = p1[fm];
        }
    }
    __syncthreads();

    if (tid < 128) {
        int il = tid >> 3, jl = tid & 7;
        float sv = s.part[tid][0] + s.part[tid][1] + s.b3s;
        out[(i0 + il) * N_TOK + (j0 + jl)] =
            (s.msi[il] + s.msj[jl] + sv) * (1.f / 3.f);
    }
}

// ---------------------------------------------------------------------------
extern "C" void kernel_launch(void* const* d_in, const int* in_sizes, int n_in,
                              void* d_out, int out_size) {
    const float* G  = (const float*)d_in[0];
    const float* ms = (const float*)d_in[1];
    const float* W1 = (const float*)d_in[2];
    const float* b1 = (const float*)d_in[3];
    const float* W2 = (const float*)d_in[4];
    const float* b2 = (const float*)d_in[5];
    const float* W3 = (const float*)d_in[6];
    const float* b3 = (const float*)d_in[7];
    float* out = (float*)d_out;

    cudaFuncSetAttribute(ab_kernel, cudaFuncAttributeMaxDynamicSharedMemorySize,
                         (int)sizeof(SmemAB));
    cudaFuncSetAttribute(pw_kernel, cudaFuncAttributeMaxDynamicSharedMemorySize,
                         (int)sizeof(SmemPW));

    wprep<<<(IMG1W + 255) / 256, 256>>>(W1, W2);
    ab_kernel<<<dim3(8, 2), 256, sizeof(SmemAB)>>>(G, W1, b1);
    pw_kernel<<<dim3(64, 32), 256, sizeof(SmemPW)>>>(G, ms, b2, W3, b3, out);
}

// round 6
// speedup vs baseline: 7.2614x; 1.0997x over previous
#include <cuda_runtime.h>
#include <cuda_fp16.h>
#include <cstdint>

#define N_TOK 512
#define E_DIM 256
#define HID   150
#define NP    152            // trimmed hidden dim (mult of 8)
#define WST   168            // weight image word stride (WST % 32 == 8 for banks)
#define PST   132            // P word stride (== 4 mod 32)
#define H1ST  84             // h1 word stride (84*4 mod 32 banks ok, proven R5)
#define IMG1W (128 * WST)    // GEMM1 weights, 128 kpairs (K=256)
#define IMG2W (80  * WST)    // GEMM2 weights, 80 kpairs  (K=160)
#define CHUNK4 672           // 16 kpairs * 168 words / 4 float4 per chunk

__device__ float    g_sA[N_TOK * NP];
__device__ float    g_sB[N_TOK * NP];
__device__ uint32_t g_img1[IMG1W];
__device__ uint32_t g_img2[IMG2W];

// ---------------- SMEM layout (bytes) ----------------
#define OFF_P    0                       // P: 128 x 132 words (67584 B); h1 aliases
#define OFF_W    67584                   // weight double buffer 2 x 16 x 168 words
#define OFF_X    89088                   // gih/gjh (12416 B) then sA/sB (14592 B)
#define OFF_B2   103680
#define OFF_W3   104288
#define OFF_MSI  104896
#define OFF_MSJ  104960
#define OFF_PART 104992                  // 128 x 2 floats
#define OFF_B3   106016
#define PW_SMEM  106048

// ---------------- helpers ----------------
__device__ __forceinline__ uint32_t packh2(float lo, float hi) {
    __half2 h = __floats2half2_rn(lo, hi);
    return *reinterpret_cast<uint32_t*>(&h);
}
__device__ __forceinline__ uint32_t hmul2u(uint32_t a, uint32_t b) {
    __half2 r = __hmul2(*reinterpret_cast<__half2*>(&a), *reinterpret_cast<__half2*>(&b));
    return *reinterpret_cast<uint32_t*>(&r);
}
__device__ __forceinline__ void mma16(float* d, uint32_t a0, uint32_t a1,
                                      uint32_t a2, uint32_t a3,
                                      uint32_t b0, uint32_t b1) {
    asm volatile(
        "mma.sync.aligned.m16n8k16.row.col.f32.f16.f16.f32 "
        "{%0,%1,%2,%3}, {%4,%5,%6,%7}, {%8,%9}, {%0,%1,%2,%3};"
        : "+f"(d[0]), "+f"(d[1]), "+f"(d[2]), "+f"(d[3])
        : "r"(a0), "r"(a1), "r"(a2), "r"(a3), "r"(b0), "r"(b1));
}
__device__ __forceinline__ void cpasync16(uint32_t dst, const float4* src) {
    asm volatile("cp.async.cg.shared.global [%0], [%1], 16;" :: "r"(dst), "l"(src));
}
#define CP_COMMIT() asm volatile("cp.async.commit_group;")
#define CP_WAIT0()  asm volatile("cp.async.wait_group 0;" ::: "memory")

__device__ __forceinline__ void stage_chunk(uint32_t smem_dst, const float4* src, int tid) {
    #pragma unroll
    for (int t = 0; t < 3; t++) {
        int idx = tid + t * 256;
        if (idx < CHUNK4) cpasync16(smem_dst + idx * 16, src + idx);
    }
    CP_COMMIT();
}

// ---------------------------------------------------------------------------
// wprep: fp16 half2 weight images [kpair][n] (k-pairs packed), pads zero.
// ---------------------------------------------------------------------------
__global__ void wprep(const float* __restrict__ W1, const float* __restrict__ W2) {
    int idx = blockIdx.x * 256 + threadIdx.x;
    if (idx < IMG1W) {
        int kp = idx / WST, n = idx - kp * WST;
        float lo = 0.f, hi = 0.f;
        if (n < HID) {
            lo = W1[(2 * E_DIM + 2 * kp)     * HID + n];
            hi = W1[(2 * E_DIM + 2 * kp + 1) * HID + n];
        }
        g_img1[idx] = packh2(lo, hi);
    }
    if (idx < IMG2W) {
        int kp = idx / WST, n = idx - kp * WST;
        float lo = 0.f, hi = 0.f;
        if (n < HID) {
            if (2 * kp     < HID) lo = W2[(2 * kp)     * HID + n];
            if (2 * kp + 1 < HID) hi = W2[(2 * kp + 1) * HID + n];
        }
        g_img2[idx] = packh2(lo, hi);
    }
}

// ---------------------------------------------------------------------------
// ab_kernel: exact fp32 sA/sB precompute (out stride NP=152, pads zero).
// ---------------------------------------------------------------------------
struct SmemAB { float g[64][E_DIM]; float w[32][160]; };

__global__ __launch_bounds__(256, 2)
void ab_kernel(const float* __restrict__ G, const float* __restrict__ W1,
               const float* __restrict__ b1) {
    extern __shared__ char smemraw[];
    SmemAB& s = *reinterpret_cast<SmemAB*>(smemraw);
    const int tid = threadIdx.x, tx = tid & 15, ty = tid >> 4;
    const int r0 = blockIdx.x * 64, variant = blockIdx.y;
    const float* W = W1 + variant * E_DIM * HID;
    float* outbuf = variant ? g_sB : g_sA;

    for (int idx = tid; idx < 64 * E_DIM; idx += 256)
        s.g[idx >> 8][idx & 255] = G[(r0 + (idx >> 8)) * E_DIM + (idx & 255)];

    float acc[4][10];
    #pragma unroll
    for (int m = 0; m < 4; m++)
        #pragma unroll
        for (int n = 0; n < 10; n++) {
            int h = tx * 10 + n;
            acc[m][n] = (variant == 0 && h < HID) ? b1[h] : 0.f;
        }
    for (int kk = 0; kk < E_DIM; kk += 32) {
        __syncthreads();
        for (int idx = tid; idx < 32 * 160; idx += 256) {
            int r = idx / 160, c = idx - r * 160;
            s.w[r][c] = (c < HID) ? W[(kk + r) * HID + c] : 0.f;
        }
        __syncthreads();
        #pragma unroll 8
        for (int e = 0; e < 32; e++) {
            float a[4];
            #pragma unroll
            for (int m = 0; m < 4; m++) a[m] = s.g[ty + 16 * m][kk + e];
            float w[10];
            #pragma unroll
            for (int n = 0; n < 10; n++) w[n] = s.w[e][tx * 10 + n];
            #pragma unroll
            for (int m = 0; m < 4; m++)
                #pragma unroll
                for (int n = 0; n < 10; n++)
                    acc[m][n] = fmaf(a[m], w[n], acc[m][n]);
        }
    }
    #pragma unroll
    for (int m = 0; m < 4; m++) {
        int r = r0 + ty + 16 * m;
        #pragma unroll
        for (int n = 0; n < 10; n++) {
            int h = tx * 10 + n;
            if (h < NP) outbuf[r * NP + h] = acc[m][n];
        }
    }
}

// ---------------------------------------------------------------------------
// pw_body: templated on NF (n8 fragments per warp): wn=0 -> 10, wn=1 -> 9.
// ---------------------------------------------------------------------------
template<int NF>
__device__ __forceinline__ void pw_body(
    char* sm, uint32_t sb, int tid, int wm, int wn, int qrow, int qk,
    int i0, int j0, float* __restrict__ out)
{
    uint32_t* P  = (uint32_t*)sm;           // GEMM1 A operand (fp16 products)
    uint32_t* h1 = (uint32_t*)sm;           // aliases P after GEMM1, stride H1ST
    float* sA   = (float*)(sm + OFF_X);
    float* sB   = sA + 16 * NP;
    float* s_b2 = (float*)(sm + OFF_B2);
    float* s_w3 = (float*)(sm + OFF_W3);
    float* msi  = (float*)(sm + OFF_MSI);
    float* msj  = (float*)(sm + OFF_MSJ);
    float* part = (float*)(sm + OFF_PART);
    const int nbase = wn * 80;
    const uint32_t wsm[2] = { sb + OFF_W, sb + OFF_W + 16 * WST * 4 };

    float acc[2][NF][4];
    #pragma unroll
    for (int fm = 0; fm < 2; fm++)
        #pragma unroll
        for (int nf = 0; nf < NF; nf++)
            #pragma unroll
            for (int q = 0; q < 4; q++) acc[fm][nf][q] = 0.f;

    const float4* img1_4 = (const float4*)g_img1;
    const float4* img2_4 = (const float4*)g_img2;

    // ---- GEMM1: acc = P @ W1c^T, K=256 = 8 chunks x 2 k16-tiles ----
    for (int c = 0; c < 8; c++) {
        stage_chunk(wsm[(c + 1) & 1],
                    (c < 7) ? (img1_4 + (c + 1) * CHUNK4) : img2_4, tid);
        const uint32_t* wb = (const uint32_t*)(sm + OFF_W) + (c & 1) * 16 * WST;
        #pragma unroll
        for (int t = 0; t < 2; t++) {
            int kw = (c * 2 + t) * 8;
            uint32_t b[NF][2];
            #pragma unroll
            for (int nf = 0; nf < NF; nf++) {
                int n = nbase + nf * 8 + qrow;
                b[nf][0] = wb[(t * 8 + qk) * WST + n];
                b[nf][1] = wb[(t * 8 + qk + 4) * WST + n];
            }
            #pragma unroll
            for (int fm = 0; fm < 2; fm++) {
                int rA = (wm * 32 + fm * 16 + qrow) * PST + kw + qk;
                uint32_t a0 = P[rA], a1 = P[rA + 8 * PST];
                uint32_t a2 = P[rA + 4], a3 = P[rA + 8 * PST + 4];
                #pragma unroll
                for (int nf = 0; nf < NF; nf++)
                    mma16(acc[fm][nf], a0, a1, a2, a3, b[nf][0], b[nf][1]);
            }
        }
        CP_WAIT0();
        __syncthreads();
    }

    // ---- h1 = relu(acc + sA_i + sB_j) as half2 -> SMEM; re-init acc = b2 ----
    #pragma unroll
    for (int fm = 0; fm < 2; fm++) {
        int r0 = wm * 32 + fm * 16 + qrow, r1 = r0 + 8;
        int il0 = wm * 4 + fm * 2;
        #pragma unroll
        for (int nf = 0; nf < NF; nf++) {
            int c0 = nbase + nf * 8 + 2 * qk, c1 = c0 + 1;
            int word = wn * 40 + nf * 4 + qk;
            float sb0 = sB[qrow * NP + c0], sb1 = sB[qrow * NP + c1];
            float v00 = acc[fm][nf][0] + sA[il0 * NP + c0] + sb0;
            float v01 = acc[fm][nf][1] + sA[il0 * NP + c1] + sb1;
            float v10 = acc[fm][nf][2] + sA[(il0 + 1) * NP + c0] + sb0;
            float v11 = acc[fm][nf][3] + sA[(il0 + 1) * NP + c1] + sb1;
            h1[r0 * H1ST + word] = packh2(fmaxf(v00, 0.f), fmaxf(v01, 0.f));
            h1[r1 * H1ST + word] = packh2(fmaxf(v10, 0.f), fmaxf(v11, 0.f));
            float w0 = s_b2[c0], w1 = s_b2[c1];
            acc[fm][nf][0] = w0; acc[fm][nf][1] = w1;
            acc[fm][nf][2] = w0; acc[fm][nf][3] = w1;
        }
    }
    if (tid < 128) {            // zero h1 words 76..79 (cols 152..159)
        uint4 z = make_uint4(0, 0, 0, 0);
        *(uint4*)&h1[tid * H1ST + 76] = z;
    }
    __syncthreads();            // h1 visible; w buf0 already holds img2 chunk 0

    // ---- GEMM2: acc += h1 @ W2^T, K=160 = 5 chunks x 2 k16-tiles ----
    for (int c = 0; c < 5; c++) {
        if (c < 4) stage_chunk(wsm[(c + 1) & 1], img2_4 + (c + 1) * CHUNK4, tid);
        const uint32_t* wb = (const uint32_t*)(sm + OFF_W) + (c & 1) * 16 * WST;
        #pragma unroll
        for (int t = 0; t < 2; t++) {
            int kw = (c * 2 + t) * 8;
            uint32_t b[NF][2];
            #pragma unroll
            for (int nf = 0; nf < NF; nf++) {
                int n = nbase + nf * 8 + qrow;
                b[nf][0] = wb[(t * 8 + qk) * WST + n];
                b[nf][1] = wb[(t * 8 + qk + 4) * WST + n];
            }
            #pragma unroll
            for (int fm = 0; fm < 2; fm++) {
                int r0 = wm * 32 + fm * 16 + qrow;
                uint32_t a0 = h1[r0 * H1ST + kw + qk];
                uint32_t a1 = h1[(r0 + 8) * H1ST + kw + qk];
                uint32_t a2 = h1[r0 * H1ST + kw + qk + 4];
                uint32_t a3 = h1[(r0 + 8) * H1ST + kw + qk + 4];
                #pragma unroll
                for (int nf = 0; nf < NF; nf++)
                    mma16(acc[fm][nf], a0, a1, a2, a3, b[nf][0], b[nf][1]);
            }
        }
        CP_WAIT0();
        __syncthreads();
    }

    // ---- layer 3: relu(h2) . W3, quad reduce, combine ----
    float p0[2] = {0.f, 0.f}, p1[2] = {0.f, 0.f};
    #pragma unroll
    for (int fm = 0; fm < 2; fm++)
        #pragma unroll
        for (int nf = 0; nf < NF; nf++) {
            int c0 = nbase + nf * 8 + 2 * qk;
            float w30 = s_w3[c0], w31 = s_w3[c0 + 1];
            p0[fm] = fmaf(fmaxf(acc[fm][nf][0], 0.f), w30,
                     fmaf(fmaxf(acc[fm][nf][1], 0.f), w31, p0[fm]));
            p1[fm] = fmaf(fmaxf(acc[fm][nf][2], 0.f), w30,
                     fmaf(fmaxf(acc[fm][nf][3], 0.f), w31, p1[fm]));
        }
    #pragma unroll
    for (int fm = 0; fm < 2; fm++) {
        #pragma unroll
        for (int off = 1; off <= 2; off <<= 1) {
            p0[fm] += __shfl_xor_sync(0xffffffffu, p0[fm], off);
            p1[fm] += __shfl_xor_sync(0xffffffffu, p1[fm], off);
        }
    }
    if (qk == 0) {
        #pragma unroll
        for (int fm = 0; fm < 2; fm++) {
            int r0 = wm * 32 + fm * 16 + qrow;
            part[r0 * 2 + wn]       = p0[fm];
            part[(r0 + 8) * 2 + wn] = p1[fm];
        }
    }
    __syncthreads();

    if (tid < 128) {
        int il = tid >> 3, jl = tid & 7;
        float b3s = *(float*)(sm + OFF_B3);
        float sv = part[tid * 2] + part[tid * 2 + 1] + b3s;
        out[(i0 + il) * N_TOK + (j0 + jl)] =
            (msi[il] + msj[jl] + sv) * (1.f / 3.f);
    }
}

// ---------------------------------------------------------------------------
// pw_kernel: 128 pairs (16 i x 8 j) per block, fp16 m16n8k16, 2 blocks/SM.
// ---------------------------------------------------------------------------
__global__ __launch_bounds__(256, 2)
void pw_kernel(const float* __restrict__ G, const float* __restrict__ ms,
               const float* __restrict__ b2, const float* __restrict__ W3,
               const float* __restrict__ b3, float* __restrict__ out) {
    extern __shared__ char sm[];
    const uint32_t sb = (uint32_t)__cvta_generic_to_shared(sm);
    const int tid  = threadIdx.x;
    const int lane = tid & 31, wid = tid >> 5;
    const int wm = wid & 3, wn = wid >> 2;
    const int qrow = lane >> 2, qk = lane & 3;
    const int i0 = blockIdx.y * 16, j0 = blockIdx.x * 8;

    // stage GEMM1 weight chunk 0 (group)
    stage_chunk(sb + OFF_W, (const float4*)g_img1, tid);

    // small params
    float* s_b2 = (float*)(sm + OFF_B2);
    float* s_w3 = (float*)(sm + OFF_W3);
    if (tid < NP) {
        s_b2[tid] = (tid < HID) ? b2[tid] : 0.f;
        s_w3[tid] = (tid < HID) ? W3[tid] : 0.f;
    }
    if (tid < 16) ((float*)(sm + OFF_MSI))[tid] = ms[i0 + tid];
    if (tid < 8)  ((float*)(sm + OFF_MSJ))[tid] = ms[j0 + tid];
    if (tid == 0) *(float*)(sm + OFF_B3) = b3[0];

    // convert G rows to fp16 (gih stride 128 broadcast-read; gjh stride 132)
    uint32_t* gih = (uint32_t*)(sm + OFF_X);
    uint32_t* gjh = gih + 16 * 128;
    const float2* G2 = (const float2*)G;
    #pragma unroll
    for (int t = 0; t < 8; t++) {
        int idx = tid + t * 256, r = idx >> 7, w = idx & 127;
        float2 f = G2[(i0 + r) * 128 + w];
        gih[r * 128 + w] = packh2(f.x, f.y);
    }
    #pragma unroll
    for (int t = 0; t < 4; t++) {
        int idx = tid + t * 256, r = idx >> 7, w = idx & 127;
        float2 f = G2[(j0 + r) * 128 + w];
        gjh[r * 132 + w] = packh2(f.x, f.y);
    }
    __syncthreads();

    // build P: 128 pairs x 128 half2 words (fragment-ready, stride PST)
    {
        uint32_t* P = (uint32_t*)sm;
        int p = tid & 127, hh = tid >> 7;
        int il = p >> 3, jl = p & 7;
        #pragma unroll
        for (int q = 0; q < 16; q++) {
            int ka = hh * 64 + q * 4;
            uint4 va = *(uint4*)&gih[il * 128 + ka];
            uint4 vb = *(uint4*)&gjh[jl * 132 + ka];
            uint4 o;
            o.x = hmul2u(va.x, vb.x);
            o.y = hmul2u(va.y, vb.y);
            o.z = hmul2u(va.z, vb.z);
            o.w = hmul2u(va.w, vb.w);
            *(uint4*)&P[p * PST + ka] = o;
        }
    }
    CP_WAIT0();          // weight chunk 0 resident
    __syncthreads();     // P ready; gih/gjh dead

    // sA/sB into X region via cp.async (consumed at h1 epilogue; first
    // in-loop CP_WAIT0 covers it)
    {
        const float4* A4 = (const float4*)g_sA + i0 * (NP / 4);
        const float4* B4 = (const float4*)g_sB + j0 * (NP / 4);
        uint32_t dstA = sb + OFF_X, dstB = dstA + 16 * NP * 4;
        #pragma unroll
        for (int t = 0; t < 3; t++) {
            int idx = tid + t * 256;
            if (idx < 16 * (NP / 4)) cpasync16(dstA + idx * 16, A4 + idx);
        }
        #pragma unroll
        for (int t = 0; t < 2; t++) {
            int idx = tid + t * 256;
            if (idx < 8 * (NP / 4)) cpasync16(dstB + idx * 16, B4 + idx);
        }
        CP_COMMIT();
    }

    if (wn == 0) pw_body<10>(sm, sb, tid, wm, 0, qrow, qk, i0, j0, out);
    else         pw_body<9> (sm, sb, tid, wm, 1, qrow, qk, i0, j0, out);
}

// ---------------------------------------------------------------------------
extern "C" void kernel_launch(void* const* d_in, const int* in_sizes, int n_in,
                              void* d_out, int out_size) {
    const float* G  = (const float*)d_in[0];
    const float* ms = (const float*)d_in[1];
    const float* W1 = (const float*)d_in[2];
    const float* b1 = (const float*)d_in[3];
    const float* W2 = (const float*)d_in[4];
    const float* b2 = (const float*)d_in[5];
    const float* W3 = (const float*)d_in[6];
    const float* b3 = (const float*)d_in[7];
    float* out = (float*)d_out;

    cudaFuncSetAttribute(ab_kernel, cudaFuncAttributeMaxDynamicSharedMemorySize,
                         (int)sizeof(SmemAB));
    cudaFuncSetAttribute(pw_kernel, cudaFuncAttributeMaxDynamicSharedMemorySize,
                         PW_SMEM);

    wprep<<<(IMG1W + 255) / 256, 256>>>(W1, W2);
    ab_kernel<<<dim3(8, 2), 256, sizeof(SmemAB)>>>(G, W1, b1);
    pw_kernel<<<dim3(64, 32), 256, PW_SMEM>>>(G, ms, b2, W3, b3, out);
}

// round 10
// speedup vs baseline: 7.2663x; 1.0007x over previous
#include <cuda_runtime.h>
#include <cuda_fp16.h>
#include <cstdint>

#define N_TOK 512
#define E_DIM 256
#define HID   150
#define NP    152            // trimmed hidden dim (mult of 8)
#define WST   168            // weight image word stride
#define PST   132            // P word stride
#define H1ST  84             // h1 word stride
#define IMG1W (128 * WST)    // GEMM1 weights, 128 kpairs (K=256)
#define IMG2W (80  * WST)    // GEMM2 weights, 80 kpairs  (K=160)
#define CHUNK4 672           // 16 kpairs * 168 words / 4 float4 per chunk

__device__ float    g_sA[N_TOK * NP];
__device__ float    g_sB[N_TOK * NP];
__device__ uint32_t g_img1[IMG1W];
__device__ uint32_t g_img2[IMG2W];

// ---------------- SMEM layout (bytes) ----------------
#define OFF_P    0                       // P: 128 x 132 words (67584 B); h1 aliases
#define OFF_W    67584                   // weight double buffer 2 x 16 x 168 words
#define OFF_X    89088                   // gih/gjh (12416 B) then sA/sB (14592 B)
#define OFF_B2   103680
#define OFF_W3   104288
#define OFF_MSI  104896
#define OFF_MSJ  104960
#define OFF_PART 104992                  // 128 x 2 floats
#define OFF_B3   106016
#define PW_SMEM  106048

// ---------------- helpers ----------------
__device__ __forceinline__ uint32_t packh2(float lo, float hi) {
    __half2 h = __floats2half2_rn(lo, hi);
    return *reinterpret_cast<uint32_t*>(&h);
}
__device__ __forceinline__ uint32_t hmul2u(uint32_t a, uint32_t b) {
    __half2 r = __hmul2(*reinterpret_cast<__half2*>(&a), *reinterpret_cast<__half2*>(&b));
    return *reinterpret_cast<uint32_t*>(&r);
}
__device__ __forceinline__ void mma16(float* d, uint32_t a0, uint32_t a1,
                                      uint32_t a2, uint32_t a3,
                                      uint32_t b0, uint32_t b1) {
    asm volatile(
        "mma.sync.aligned.m16n8k16.row.col.f32.f16.f16.f32 "
        "{%0,%1,%2,%3}, {%4,%5,%6,%7}, {%8,%9}, {%0,%1,%2,%3};"
        : "+f"(d[0]), "+f"(d[1]), "+f"(d[2]), "+f"(d[3])
        : "r"(a0), "r"(a1), "r"(a2), "r"(a3), "r"(b0), "r"(b1));
}
__device__ __forceinline__ void cpasync16(uint32_t dst, const float4* src) {
    asm volatile("cp.async.cg.shared.global [%0], [%1], 16;" :: "r"(dst), "l"(src));
}
#define CP_COMMIT() asm volatile("cp.async.commit_group;")
#define CP_WAIT0()  asm volatile("cp.async.wait_group 0;" ::: "memory")

__device__ __forceinline__ void stage_chunk(uint32_t smem_dst, const float4* src, int tid) {
    #pragma unroll
    for (int t = 0; t < 3; t++) {
        int idx = tid + t * 256;
        if (idx < CHUNK4) cpasync16(smem_dst + idx * 16, src + idx);
    }
    CP_COMMIT();
}

// ---------------------------------------------------------------------------
// prep: merged wprep + ab_kernel.
//   blocks 0..15  : sA/sB precompute (exact fp32), variant = bid&1, r0 = (bid>>1)*64
//   blocks 16..99 : fp16 weight image build (84 blocks x 256 threads = 21504)
// ---------------------------------------------------------------------------
struct SmemAB { float g[64][E_DIM]; float w[32][160]; };

__global__ __launch_bounds__(256, 2)
void prep(const float* __restrict__ G, const float* __restrict__ W1,
          const float* __restrict__ W2, const float* __restrict__ b1) {
    const int bid = blockIdx.x, tid = threadIdx.x;

    if (bid >= 16) {
        // ---- weight image build (identical formulas to R6 wprep) ----
        int idx = (bid - 16) * 256 + tid;
        if (idx < IMG1W) {
            int kp = idx / WST, n = idx - kp * WST;
            float lo = 0.f, hi = 0.f;
            if (n < HID) {
                lo = W1[(2 * E_DIM + 2 * kp)     * HID + n];
                hi = W1[(2 * E_DIM + 2 * kp + 1) * HID + n];
            }
            g_img1[idx] = packh2(lo, hi);
        }
        if (idx < IMG2W) {
            int kp = idx / WST, n = idx - kp * WST;
            float lo = 0.f, hi = 0.f;
            if (n < HID) {
                if (2 * kp     < HID) lo = W2[(2 * kp)     * HID + n];
                if (2 * kp + 1 < HID) hi = W2[(2 * kp + 1) * HID + n];
            }
            g_img2[idx] = packh2(lo, hi);
        }
        return;
    }

    // ---- sA/sB precompute (identical to R6 ab_kernel) ----
    extern __shared__ char smemraw[];
    SmemAB& s = *reinterpret_cast<SmemAB*>(smemraw);
    const int tx = tid & 15, ty = tid >> 4;
    const int r0 = (bid >> 1) * 64, variant = bid & 1;
    const float* W = W1 + variant * E_DIM * HID;
    float* outbuf = variant ? g_sB : g_sA;

    for (int idx = tid; idx < 64 * E_DIM; idx += 256)
        s.g[idx >> 8][idx & 255] = G[(r0 + (idx >> 8)) * E_DIM + (idx & 255)];

    float acc[4][10];
    #pragma unroll
    for (int m = 0; m < 4; m++)
        #pragma unroll
        for (int n = 0; n < 10; n++) {
            int h = tx * 10 + n;
            acc[m][n] = (variant == 0 && h < HID) ? b1[h] : 0.f;
        }
    for (int kk = 0; kk < E_DIM; kk += 32) {
        __syncthreads();
        for (int idx = tid; idx < 32 * 160; idx += 256) {
            int r = idx / 160, c = idx - r * 160;
            s.w[r][c] = (c < HID) ? W[(kk + r) * HID + c] : 0.f;
        }
        __syncthreads();
        #pragma unroll 8
        for (int e = 0; e < 32; e++) {
            float a[4];
            #pragma unroll
            for (int m = 0; m < 4; m++) a[m] = s.g[ty + 16 * m][kk + e];
            float w[10];
            #pragma unroll
            for (int n = 0; n < 10; n++) w[n] = s.w[e][tx * 10 + n];
            #pragma unroll
            for (int m = 0; m < 4; m++)
                #pragma unroll
                for (int n = 0; n < 10; n++)
                    acc[m][n] = fmaf(a[m], w[n], acc[m][n]);
        }
    }
    #pragma unroll
    for (int m = 0; m < 4; m++) {
        int r = r0 + ty + 16 * m;
        #pragma unroll
        for (int n = 0; n < 10; n++) {
            int h = tx * 10 + n;
            if (h < NP) outbuf[r * NP + h] = acc[m][n];
        }
    }
}

// ---------------------------------------------------------------------------
// pw_body: templated on NF (n8 fragments per warp): wn=0 -> 10, wn=1 -> 9.
// (byte-identical logic to round 6)
// ---------------------------------------------------------------------------
template<int NF>
__device__ __forceinline__ void pw_body(
    char* sm, uint32_t sb, int tid, int wm, int wn, int qrow, int qk,
    int i0, int j0, float* __restrict__ out)
{
    uint32_t* P  = (uint32_t*)sm;           // GEMM1 A operand (fp16 products)
    uint32_t* h1 = (uint32_t*)sm;           // aliases P after GEMM1, stride H1ST
    float* sA   = (float*)(sm + OFF_X);
    float* sB   = sA + 16 * NP;
    float* s_b2 = (float*)(sm + OFF_B2);
    float* s_w3 = (float*)(sm + OFF_W3);
    float* msi  = (float*)(sm + OFF_MSI);
    float* msj  = (float*)(sm + OFF_MSJ);
    float* part = (float*)(sm + OFF_PART);
    const int nbase = wn * 80;
    const uint32_t wsm[2] = { sb + OFF_W, sb + OFF_W + 16 * WST * 4 };

    float acc[2][NF][4];
    #pragma unroll
    for (int fm = 0; fm < 2; fm++)
        #pragma unroll
        for (int nf = 0; nf < NF; nf++)
            #pragma unroll
            for (int q = 0; q < 4; q++) acc[fm][nf][q] = 0.f;

    const float4* img1_4 = (const float4*)g_img1;
    const float4* img2_4 = (const float4*)g_img2;

    // ---- GEMM1: acc = P @ W1c^T, K=256 = 8 chunks x 2 k16-tiles ----
    for (int c = 0; c < 8; c++) {
        stage_chunk(wsm[(c + 1) & 1],
                    (c < 7) ? (img1_4 + (c + 1) * CHUNK4) : img2_4, tid);
        const uint32_t* wb = (const uint32_t*)(sm + OFF_W) + (c & 1) * 16 * WST;
        #pragma unroll
        for (int t = 0; t < 2; t++) {
            int kw = (c * 2 + t) * 8;
            uint32_t b[NF][2];
            #pragma unroll
            for (int nf = 0; nf < NF; nf++) {
                int n = nbase + nf * 8 + qrow;
                b[nf][0] = wb[(t * 8 + qk) * WST + n];
                b[nf][1] = wb[(t * 8 + qk + 4) * WST + n];
            }
            #pragma unroll
            for (int fm = 0; fm < 2; fm++) {
                int rA = (wm * 32 + fm * 16 + qrow) * PST + kw + qk;
                uint32_t a0 = P[rA], a1 = P[rA + 8 * PST];
                uint32_t a2 = P[rA + 4], a3 = P[rA + 8 * PST + 4];
                #pragma unroll
                for (int nf = 0; nf < NF; nf++)
                    mma16(acc[fm][nf], a0, a1, a2, a3, b[nf][0], b[nf][1]);
            }
        }
        CP_WAIT0();
        __syncthreads();
    }

    // ---- h1 = relu(acc + sA_i + sB_j) as half2; re-init acc = b2 ----
    #pragma unroll
    for (int fm = 0; fm < 2; fm++) {
        int r0 = wm * 32 + fm * 16 + qrow, r1 = r0 + 8;
        int il0 = wm * 4 + fm * 2;
        #pragma unroll
        for (int nf = 0; nf < NF; nf++) {
            int c0 = nbase + nf * 8 + 2 * qk, c1 = c0 + 1;
            int word = wn * 40 + nf * 4 + qk;
            float sb0 = sB[qrow * NP + c0], sb1 = sB[qrow * NP + c1];
            float v00 = acc[fm][nf][0] + sA[il0 * NP + c0] + sb0;
            float v01 = acc[fm][nf][1] + sA[il0 * NP + c1] + sb1;
            float v10 = acc[fm][nf][2] + sA[(il0 + 1) * NP + c0] + sb0;
            float v11 = acc[fm][nf][3] + sA[(il0 + 1) * NP + c1] + sb1;
            h1[r0 * H1ST + word] = packh2(fmaxf(v00, 0.f), fmaxf(v01, 0.f));
            h1[r1 * H1ST + word] = packh2(fmaxf(v10, 0.f), fmaxf(v11, 0.f));
            float w0 = s_b2[c0], w1 = s_b2[c1];
            acc[fm][nf][0] = w0; acc[fm][nf][1] = w1;
            acc[fm][nf][2] = w0; acc[fm][nf][3] = w1;
        }
    }
    {   // zero pad words 76..79 (cols 152..159)
        int r = wm * 32 + (tid & 31);
        *(uint4*)&h1[r * H1ST + 76] = make_uint4(0, 0, 0, 0);
    }
    __syncthreads();   // h1 visible; w buf0 already holds img2 chunk 0

    // ---- GEMM2: acc += h1 @ W2^T, K=160 = 5 chunks x 2 k16-tiles ----
    for (int c = 0; c < 5; c++) {
        if (c < 4) stage_chunk(wsm[(c + 1) & 1], img2_4 + (c + 1) * CHUNK4, tid);
        const uint32_t* wb = (const uint32_t*)(sm + OFF_W) + (c & 1) * 16 * WST;
        #pragma unroll
        for (int t = 0; t < 2; t++) {
            int kw = (c * 2 + t) * 8;
            uint32_t b[NF][2];
            #pragma unroll
            for (int nf = 0; nf < NF; nf++) {
                int n = nbase + nf * 8 + qrow;
                b[nf][0] = wb[(t * 8 + qk) * WST + n];
                b[nf][1] = wb[(t * 8 + qk + 4) * WST + n];
            }
            #pragma unroll
            for (int fm = 0; fm < 2; fm++) {
                int r0 = wm * 32 + fm * 16 + qrow;
                uint32_t a0 = h1[r0 * H1ST + kw + qk];
                uint32_t a1 = h1[(r0 + 8) * H1ST + kw + qk];
                uint32_t a2 = h1[r0 * H1ST + kw + qk + 4];
                uint32_t a3 = h1[(r0 + 8) * H1ST + kw + qk + 4];
                #pragma unroll
                for (int nf = 0; nf < NF; nf++)
                    mma16(acc[fm][nf], a0, a1, a2, a3, b[nf][0], b[nf][1]);
            }
        }
        CP_WAIT0();
        __syncthreads();
    }

    // ---- layer 3: relu(h2).W3, quad reduce, combine ----
    float p0[2] = {0.f, 0.f}, p1[2] = {0.f, 0.f};
    #pragma unroll
    for (int fm = 0; fm < 2; fm++)
        #pragma unroll
        for (int nf = 0; nf < NF; nf++) {
            int c0 = nbase + nf * 8 + 2 * qk;
            float w30 = s_w3[c0], w31 = s_w3[c0 + 1];
            p0[fm] = fmaf(fmaxf(acc[fm][nf][0], 0.f), w30,
                     fmaf(fmaxf(acc[fm][nf][1], 0.f), w31, p0[fm]));
            p1[fm] = fmaf(fmaxf(acc[fm][nf][2], 0.f), w30,
                     fmaf(fmaxf(acc[fm][nf][3], 0.f), w31, p1[fm]));
        }
    #pragma unroll
    for (int fm = 0; fm < 2; fm++) {
        #pragma unroll
        for (int off = 1; off <= 2; off <<= 1) {
            p0[fm] += __shfl_xor_sync(0xffffffffu, p0[fm], off);
            p1[fm] += __shfl_xor_sync(0xffffffffu, p1[fm], off);
        }
    }
    if (qk == 0) {
        #pragma unroll
        for (int fm = 0; fm < 2; fm++) {
            int r0 = wm * 32 + fm * 16 + qrow;
            part[r0 * 2 + wn]       = p0[fm];
            part[(r0 + 8) * 2 + wn] = p1[fm];
        }
    }
    __syncthreads();

    if (tid < 128) {
        int il = tid >> 3, jl = tid & 7;
        float b3s = *(float*)(sm + OFF_B3);
        float sv = part[tid * 2] + part[tid * 2 + 1] + b3s;
        out[(i0 + il) * N_TOK + (j0 + jl)] =
            (msi[il] + msj[jl] + sv) * (1.f / 3.f);
    }
}

// ---------------------------------------------------------------------------
// pw_kernel: 128 pairs (16 i x 8 j) per block, fp16 m16n8k16, 2 blocks/SM.
// (byte-identical logic to round 6)
// ---------------------------------------------------------------------------
__global__ __launch_bounds__(256, 2)
void pw_kernel(const float* __restrict__ G, const float* __restrict__ ms,
               const float* __restrict__ b2, const float* __restrict__ W3,
               const float* __restrict__ b3, float* __restrict__ out) {
    extern __shared__ char sm[];
    const uint32_t sb = (uint32_t)__cvta_generic_to_shared(sm);
    const int tid  = threadIdx.x;
    const int lane = tid & 31, wid = tid >> 5;
    const int wm = wid & 3, wn = wid >> 2;
    const int qrow = lane >> 2, qk = lane & 3;
    const int i0 = blockIdx.y * 16, j0 = blockIdx.x * 8;

    // stage GEMM1 weight chunk 0 (group)
    stage_chunk(sb + OFF_W, (const float4*)g_img1, tid);

    // small params
    float* s_b2 = (float*)(sm + OFF_B2);
    float* s_w3 = (float*)(sm + OFF_W3);
    if (tid < NP) {
        s_b2[tid] = (tid < HID) ? b2[tid] : 0.f;
        s_w3[tid] = (tid < HID) ? W3[tid] : 0.f;
    }
    if (tid < 16) ((float*)(sm + OFF_MSI))[tid] = ms[i0 + tid];
    if (tid < 8)  ((float*)(sm + OFF_MSJ))[tid] = ms[j0 + tid];
    if (tid == 0) *(float*)(sm + OFF_B3) = b3[0];

    // convert G rows to fp16 (gih stride 128 broadcast-read; gjh stride 132)
    uint32_t* gih = (uint32_t*)(sm + OFF_X);
    uint32_t* gjh = gih + 16 * 128;
    const float2* G2 = (const float2*)G;
    #pragma unroll
    for (int t = 0; t < 8; t++) {
        int idx = tid + t * 256, r = idx >> 7, w = idx & 127;
        float2 f = G2[(i0 + r) * 128 + w];
        gih[r * 128 + w] = packh2(f.x, f.y);
    }
    #pragma unroll
    for (int t = 0; t < 4; t++) {
        int idx = tid + t * 256, r = idx >> 7, w = idx & 127;
        float2 f = G2[(j0 + r) * 128 + w];
        gjh[r * 132 + w] = packh2(f.x, f.y);
    }
    __syncthreads();

    // build P: 128 pairs x 128 half2 words (fragment-ready, stride PST)
    {
        uint32_t* P = (uint32_t*)sm;
        int p = tid & 127, hh = tid >> 7;
        int il = p >> 3, jl = p & 7;
        #pragma unroll
        for (int q = 0; q < 16; q++) {
            int ka = hh * 64 + q * 4;
            uint4 va = *(uint4*)&gih[il * 128 + ka];
            uint4 vb = *(uint4*)&gjh[jl * 132 + ka];
            uint4 o;
            o.x = hmul2u(va.x, vb.x);
            o.y = hmul2u(va.y, vb.y);
            o.z = hmul2u(va.z, vb.z);
            o.w = hmul2u(va.w, vb.w);
            *(uint4*)&P[p * PST + ka] = o;
        }
    }
    CP_WAIT0();          // weight chunk 0 resident
    __syncthreads();     // P ready; gih/gjh dead

    // sA/sB into X region via cp.async (consumed at h1 epilogue; first
    // in-loop CP_WAIT0 covers it)
    {
        const float4* A4 = (const float4*)g_sA + i0 * (NP / 4);
        const float4* B4 = (const float4*)g_sB + j0 * (NP / 4);
        uint32_t dstA = sb + OFF_X, dstB = dstA + 16 * NP * 4;
        #pragma unroll
        for (int t = 0; t < 3; t++) {
            int idx = tid + t * 256;
            if (idx < 16 * (NP / 4)) cpasync16(dstA + idx * 16, A4 + idx);
        }
        #pragma unroll
        for (int t = 0; t < 2; t++) {
            int idx = tid + t * 256;
            if (idx < 8 * (NP / 4)) cpasync16(dstB + idx * 16, B4 + idx);
        }
        CP_COMMIT();
    }

    if (wn == 0) pw_body<10>(sm, sb, tid, wm, 0, qrow, qk, i0, j0, out);
    else         pw_body<9> (sm, sb, tid, wm, 1, qrow, qk, i0, j0, out);
}

// ---------------------------------------------------------------------------
extern "C" void kernel_launch(void* const* d_in, const int* in_sizes, int n_in,
                              void* d_out, int out_size) {
    const float* G  = (const float*)d_in[0];
    const float* ms = (const float*)d_in[1];
    const float* W1 = (const float*)d_in[2];
    const float* b1 = (const float*)d_in[3];
    const float* W2 = (const float*)d_in[4];
    const float* b2 = (const float*)d_in[5];
    const float* W3 = (const float*)d_in[6];
    const float* b3 = (const float*)d_in[7];
    float* out = (float*)d_out;

    cudaFuncSetAttribute(prep, cudaFuncAttributeMaxDynamicSharedMemorySize,
                         (int)sizeof(SmemAB));
    cudaFuncSetAttribute(pw_kernel, cudaFuncAttributeMaxDynamicSharedMemorySize,
                         PW_SMEM);

    prep<<<100, 256, sizeof(SmemAB)>>>(G, W1, W2, b1);
    pw_kernel<<<dim3(64, 32), 256, PW_SMEM>>>(G, ms, b2, W3, b3, out);
}